// round 10
// baseline (speedup 1.0000x reference)
#include <cuda_runtime.h>
#include <cuda_bf16.h>
#include <cstdint>

// Problem constants (fixed shapes)
#define XDIM 362
#define GRID_STRIDE 19
#define MAXB 65536
#define RPC 128                       // rows per CTA (M tile)

// ---------------- device scratch ----------------
__device__ float g_att[MAXB * 8];
__device__ int   g_idx[MAXB * 8];
__device__ int   g_perm[3 * MAXB];    // fixed per-action regions
__device__ int   g_slot[3];           // per-action counts (append cursors)
__device__ int   g_blkb[4];           // per-action block bases (in K4 blocks)

// pre-split weight planes (bf16 hi/lo), panel-ready layouts
// W2 planes: [A][112][400]  (k zero-padded 100->112)
// W3 planes: [A][400][112]  (n zero-padded 100->112)
#define W2P (3*112*400)
#define W3P (3*400*112)
__device__ __nv_bfloat16 g_w2h[W2P];
__device__ __nv_bfloat16 g_w2l[W2P];
__device__ __nv_bfloat16 g_w3h[W3P];
__device__ __nv_bfloat16 g_w3l[W3P];

// ---------------- small helpers ----------------
__device__ __forceinline__ int clampi(int v) {
    v = v < 1 ? 1 : v;
    return v > (XDIM - 1) ? (XDIM - 1) : v;
}
__device__ __forceinline__ uint32_t smem_u32(const void* p) {
    return (uint32_t)__cvta_generic_to_shared(p);
}
__device__ __forceinline__ void bsplit(float v, __nv_bfloat16& h, __nv_bfloat16& l) {
    h = __float2bfloat16_rn(v);
    l = __float2bfloat16_rn(v - __bfloat162float(h));
}
__device__ __forceinline__ uint32_t bf16bits(__nv_bfloat16 h) {
    __nv_bfloat16_raw r = static_cast<__nv_bfloat16_raw>(h);
    return (uint32_t)r.x;
}
__device__ __forceinline__ void cp_async16(void* smem, const void* gmem) {
    unsigned s = (unsigned)__cvta_generic_to_shared(smem);
    asm volatile("cp.async.cg.shared.global [%0], [%1], 16;\n" :: "r"(s), "l"(gmem));
}
__device__ __forceinline__ void cp_commit() { asm volatile("cp.async.commit_group;\n"); }
__device__ __forceinline__ void cp_wait1() { asm volatile("cp.async.wait_group 1;\n"); }
__device__ __forceinline__ void cp_wait0() { asm volatile("cp.async.wait_group 0;\n"); }

// ---------------- mma / ldmatrix ----------------
__device__ __forceinline__ void mma16816(float* d, const uint32_t* a, const uint32_t* b) {
    asm volatile(
        "mma.sync.aligned.m16n8k16.row.col.f32.bf16.bf16.f32 "
        "{%0,%1,%2,%3}, {%4,%5,%6,%7}, {%8,%9}, {%0,%1,%2,%3};"
        : "+f"(d[0]), "+f"(d[1]), "+f"(d[2]), "+f"(d[3])
        : "r"(a[0]), "r"(a[1]), "r"(a[2]), "r"(a[3]), "r"(b[0]), "r"(b[1]));
}
__device__ __forceinline__ void ldmx4(uint32_t* r, uint32_t addr) {
    asm volatile("ldmatrix.sync.aligned.m8n8.x4.shared.b16 {%0,%1,%2,%3}, [%4];"
                 : "=r"(r[0]), "=r"(r[1]), "=r"(r[2]), "=r"(r[3]) : "r"(addr));
}
// x4 trans -> fragments for TWO adjacent n-tiles
__device__ __forceinline__ void ldmx4t(uint32_t* r, uint32_t addr) {
    asm volatile("ldmatrix.sync.aligned.m8n8.x4.trans.shared.b16 {%0,%1,%2,%3}, [%4];"
                 : "=r"(r[0]), "=r"(r[1]), "=r"(r[2]), "=r"(r[3]) : "r"(addr));
}

// ---------------- K_wsplit: pre-split W2/W3 + zero cursors ----------------
__global__ void k_wsplit(const float* __restrict__ W2, const float* __restrict__ W3) {
    int i = blockIdx.x * blockDim.x + threadIdx.x;
    if (i < 3) g_slot[i] = 0;
    if (i < W2P) {
        int a = i / (112 * 400);
        int rem = i % (112 * 400);
        int k = rem / 400, n = rem % 400;
        float v = (k < 100) ? W2[a * 40000 + k * 400 + n] : 0.f;
        __nv_bfloat16 h, l; bsplit(v, h, l);
        g_w2h[i] = h; g_w2l[i] = l;
    }
    if (i < W3P) {
        int a = i / (400 * 112);
        int rem = i % (400 * 112);
        int k = rem / 112, n = rem % 112;
        float v = (n < 100) ? W3[a * 40000 + k * 100 + n] : 0.f;
        __nv_bfloat16 h, l; bsplit(v, h, l);
        g_w3h[i] = h; g_w3l[i] = l;
    }
}

// ---------------- K1: copy x->out, argmax, gather, direct bucket append -------
__global__ void k1_prep(const float* __restrict__ x, const int* __restrict__ act,
                        float* __restrict__ out, int B) {
    __shared__ int s_cnt[3];
    __shared__ int s_base[3];
    __shared__ int s_local[8];
    __shared__ int s_act[8];
    if (threadIdx.x < 3) s_cnt[threadIdx.x] = 0;
    __syncthreads();

    int warp = (blockIdx.x * blockDim.x + threadIdx.x) >> 5;
    int wl = (threadIdx.x >> 5);
    int lane = threadIdx.x & 31;

    if (warp < B) {
        const float* xr = x + (size_t)warp * XDIM;
        float* outr = out + (size_t)warp * XDIM;
        float best = -3.402823466e+38f;
        int bidx = 0;
        for (int i = lane; i < XDIM; i += 32) {
            float v = xr[i];
            outr[i] = v;
            if (v > best) { best = v; bidx = i; }
        }
        #pragma unroll
        for (int off = 16; off; off >>= 1) {
            float ov = __shfl_xor_sync(0xffffffffu, best, off);
            int   oi = __shfl_xor_sync(0xffffffffu, bidx, off);
            if (ov > best || (ov == best && oi < bidx)) { best = ov; bidx = oi; }
        }
        if (lane == 0) {
            int ptr = bidx;
            int id[6];
            id[0] = 0;
            id[1] = ptr;                        // unclamped, as in source
            id[2] = clampi(ptr - GRID_STRIDE);
            id[3] = clampi(ptr + GRID_STRIDE);
            id[4] = clampi(ptr - 1);
            id[5] = clampi(ptr + 1);
            #pragma unroll
            for (int j = 0; j < 6; j++) {
                g_idx[warp * 8 + j] = id[j];
                g_att[warp * 8 + j] = xr[id[j]];
            }
            int a = act[warp];
            s_act[wl] = a;
            s_local[wl] = atomicAdd(&s_cnt[a], 1);
        }
    }
    __syncthreads();
    if (threadIdx.x < 3 && s_cnt[threadIdx.x] > 0)
        s_base[threadIdx.x] = atomicAdd(&g_slot[threadIdx.x], s_cnt[threadIdx.x]);
    __syncthreads();
    if (warp < B && lane == 0) {
        int a = s_act[wl];
        g_perm[a * MAXB + s_base[a] + s_local[wl]] = warp;
    }
}

// ---------------- K2: per-action block bases ----------------
__global__ void k2_bases() {
    if (threadIdx.x == 0) {
        int nb0 = (g_slot[0] + RPC - 1) / RPC;
        int nb1 = (g_slot[1] + RPC - 1) / RPC;
        int nb2 = (g_slot[2] + RPC - 1) / RPC;
        g_blkb[0] = 0;
        g_blkb[1] = nb0;
        g_blkb[2] = nb0 + nb1;
        g_blkb[3] = nb0 + nb1 + nb2;
    }
}

// ---------------- K4: fused MLP, n-split warps, double-buffered panels --------
#define KPAD2 120      // A2 row stride (bf16)
#define NPAD2 72       // B2 panel row stride (bf16), 144B
#define NPAD3 120      // B3 panel row stride (bf16), 240B
#define H3PAD 112

// panel buffer: B2H(16128) B2L(16128) B3H(15360) B3L(15360) = 62976 bytes
#define PNL_B2H 0
#define PNL_B2L 16128
#define PNL_B3H 32256
#define PNL_B3L 47616
#define PNL_STRIDE 62976

#define OFF_A2H  0
#define OFF_A2L  30720
#define OFF_P0   61440
#define OFF_D3   124416          // aliases panel buf1 (57344 <= 62976)
#define OFF_B2S  187392          // 400 f
#define OFF_B3S  188992          // 100 f (pad to 448B)
#define OFF_W1S  189440          // 700 f
#define OFF_W4S  192240          // 608 f
#define OFF_ATT  194672          // 128*8 f
#define OFF_PRED 198768          // 128*6 f
#define OFF_IDX  201840          // 128*8 i
#define OFF_ROW  205936          // 128 i
#define SMEM_TOTAL 206448

__global__ void __launch_bounds__(512, 1)
k4_mlp(const float* __restrict__ W1, const float* __restrict__ b1,
       const float* __restrict__ b2, const float* __restrict__ b3,
       const float* __restrict__ W4, const float* __restrict__ b4,
       float* __restrict__ out) {
    const int bid = blockIdx.x;
    if (bid >= g_blkb[3]) return;
    extern __shared__ char smem[];
    const uint32_t sb = smem_u32(smem);

    __nv_bfloat16* a2h = (__nv_bfloat16*)(smem + OFF_A2H);
    __nv_bfloat16* a2l = (__nv_bfloat16*)(smem + OFF_A2L);
    float* s_d3   = (float*)(smem + OFF_D3);
    float* s_b2   = (float*)(smem + OFF_B2S);
    float* s_b3   = (float*)(smem + OFF_B3S);
    float* s_w1   = (float*)(smem + OFF_W1S);
    float* s_w4   = (float*)(smem + OFF_W4S);
    float* s_att  = (float*)(smem + OFF_ATT);
    float* s_pred = (float*)(smem + OFF_PRED);
    int*   s_idx  = (int*)(smem + OFF_IDX);
    int*   s_row  = (int*)(smem + OFF_ROW);

    const int t = threadIdx.x;
    const int lane = t & 31;
    const int wid = t >> 5;           // 0..15
    const int half = wid >> 3;        // n-half 0/1
    const int wl = wid & 7;           // m-strip
    const int gid = lane >> 2;
    const int tid4 = lane & 3;

    const int a = (bid >= g_blkb[2]) ? 2 : (bid >= g_blkb[1]) ? 1 : 0;
    const int lstart = (bid - g_blkb[a]) * RPC;
    const int cnt = g_slot[a];

    const __nv_bfloat16* w2hg = g_w2h + a * 112 * 400;
    const __nv_bfloat16* w2lg = g_w2l + a * 112 * 400;
    const __nv_bfloat16* w3hg = g_w3h + a * 400 * 112;
    const __nv_bfloat16* w3lg = g_w3l + a * 400 * 112;

    // panel stager (all 512 threads), one cp.async commit group per chunk
    auto stage_chunk = [&](int c) {
        const int cbase = c * 64;
        const int width = (c < 6) ? 64 : 16;
        const int nseg2 = width >> 3;
        __nv_bfloat16* buf = (__nv_bfloat16*)(smem + OFF_P0 + (c & 1) * PNL_STRIDE);
        for (int i = t; i < 112 * nseg2; i += 512) {
            int k = i / nseg2, seg = i % nseg2;
            cp_async16(buf + (PNL_B2H/2) + k * NPAD2 + seg * 8, w2hg + k * 400 + cbase + seg * 8);
            cp_async16(buf + (PNL_B2L/2) + k * NPAD2 + seg * 8, w2lg + k * 400 + cbase + seg * 8);
        }
        for (int i = t; i < width * 14; i += 512) {
            int kl = i / 14, seg = i % 14;
            cp_async16(buf + (PNL_B3H/2) + kl * NPAD3 + seg * 8, w3hg + (cbase + kl) * 112 + seg * 8);
            cp_async16(buf + (PNL_B3L/2) + kl * NPAD3 + seg * 8, w3lg + (cbase + kl) * 112 + seg * 8);
        }
        cp_commit();
    };

    // ---- prefetch chunk 0 panels immediately ----
    stage_chunk(0);

    // ---- stage small params + row metadata, zero A2 pads ----
    for (int i = t; i < 600; i += 512) s_w1[i] = W1[a * 600 + i];
    for (int i = t; i < 100; i += 512) s_w1[600 + i] = b1[a * 100 + i];
    for (int i = t; i < 600; i += 512) s_w4[i] = W4[a * 600 + i];
    if (t < 6) s_w4[600 + t] = b4[a * 6 + t];
    for (int i = t; i < 400; i += 512) s_b2[i] = b2[a * 400 + i];
    for (int i = t; i < 100; i += 512) s_b3[i] = b3[a * 100 + i];
    for (int i = t; i < 128 * 20; i += 512) {
        int r = i / 20, c = 100 + i % 20;
        a2h[r * KPAD2 + c] = __float2bfloat16(0.f);
        a2l[r * KPAD2 + c] = __float2bfloat16(0.f);
    }
    if (t < RPC) {
        int row = (lstart + t < cnt) ? g_perm[a * MAXB + lstart + t] : -1;
        s_row[t] = row;
        if (row >= 0) {
            #pragma unroll
            for (int j = 0; j < 8; j++) {
                s_att[t * 8 + j] = g_att[row * 8 + j];
                s_idx[t * 8 + j] = g_idx[row * 8 + j];
            }
        } else {
            #pragma unroll
            for (int j = 0; j < 8; j++) { s_att[t * 8 + j] = 0.f; s_idx[t * 8 + j] = 0; }
        }
    }
    __syncthreads();

    // ---- layer 1 on cores: att[128,6] -> h1[128,100], split into A2 panels ----
    for (int o = t; o < RPC * 100; o += 512) {
        int r = o / 100, c = o % 100;
        float acc = s_w1[600 + c];
        #pragma unroll
        for (int k = 0; k < 6; k++) acc += s_att[r * 8 + k] * s_w1[k * 100 + c];
        float v = fmaxf(acc, 0.f);
        __nv_bfloat16 hb, lb; bsplit(v, hb, lb);
        a2h[r * KPAD2 + c] = hb;
        a2l[r * KPAD2 + c] = lb;
    }

    // ---- fused layers 2+3: all warps every chunk, n-split by warpgroup ----
    float acc3[14][4];
    #pragma unroll
    for (int j = 0; j < 14; j++) { acc3[j][0]=0.f; acc3[j][1]=0.f; acc3[j][2]=0.f; acc3[j][3]=0.f; }

    const int mrow = 16 * wl;
    const uint32_t nofs = (uint32_t)((lane & 16) >> 1);   // 0 or 8 for x4-trans

    for (int c = 0; c < 7; c++) {
        if (c + 1 < 7) { stage_chunk(c + 1); cp_wait1(); }
        else           { cp_wait0(); }
        __syncthreads();   // chunk-c panels visible; layer1/A2 writes visible at c==0

        const int cbase = c * 64;
        const int width = (c < 6) ? 64 : 16;
        int mycols = width - half * 32;
        mycols = (mycols < 0) ? 0 : (mycols > 32 ? 32 : mycols);
        const int npairs = mycols >> 4;     // 2, 1, or 0
        const uint32_t pnl = sb + OFF_P0 + (uint32_t)((c & 1) * PNL_STRIDE);

        if (npairs > 0) {
            // -- layer 2: acc2[2*npairs][4] over K2=112 (7 ksteps) --
            float acc2[4][4];
            #pragma unroll
            for (int j = 0; j < 4; j++) {
                if (j < 2 * npairs) {
                    float bv0 = s_b2[cbase + half * 32 + 8 * j + tid4 * 2];
                    float bv1 = s_b2[cbase + half * 32 + 8 * j + tid4 * 2 + 1];
                    acc2[j][0] = bv0; acc2[j][1] = bv1; acc2[j][2] = bv0; acc2[j][3] = bv1;
                }
            }
            const uint32_t arow = (uint32_t)(mrow + (lane & 15));
            const uint32_t acolofs = (uint32_t)((lane >> 4) << 3);
            #pragma unroll
            for (int ks = 0; ks < 7; ks++) {
                uint32_t ah[4], al[4];
                uint32_t acol = (uint32_t)(ks * 16) + acolofs;
                ldmx4(ah, sb + OFF_A2H + (arow * KPAD2 + acol) * 2);
                ldmx4(al, sb + OFF_A2L + (arow * KPAD2 + acol) * 2);
                const uint32_t krow = (uint32_t)(ks * 16 + (lane & 15));
                #pragma unroll
                for (int jp = 0; jp < 2; jp++) {
                    if (jp < npairs) {
                        uint32_t bh[4], bl[4];
                        uint32_t boff = (krow * NPAD2 + (uint32_t)(half * 32 + jp * 16) + nofs) * 2;
                        ldmx4t(bh, pnl + PNL_B2H + boff);
                        ldmx4t(bl, pnl + PNL_B2L + boff);
                        mma16816(acc2[2*jp],   ah, bh);
                        mma16816(acc2[2*jp+1], ah, bh + 2);
                        mma16816(acc2[2*jp],   ah, bl);
                        mma16816(acc2[2*jp+1], ah, bl + 2);
                        mma16816(acc2[2*jp],   al, bh);
                        mma16816(acc2[2*jp+1], al, bh + 2);
                    }
                }
            }

            // -- relu + bf16-split in regs -> A3 frags; layer 3 accumulate --
            #pragma unroll
            for (int g = 0; g < 2; g++) {
                if (g < npairs) {
                    float v0, v1;
                    uint32_t a3h[4], a3l[4];
                    __nv_bfloat16 h0, l0, h1, l1;
                    v0 = fmaxf(acc2[2*g][0], 0.f);   v1 = fmaxf(acc2[2*g][1], 0.f);
                    bsplit(v0, h0, l0); bsplit(v1, h1, l1);
                    a3h[0] = bf16bits(h0) | (bf16bits(h1) << 16);
                    a3l[0] = bf16bits(l0) | (bf16bits(l1) << 16);
                    v0 = fmaxf(acc2[2*g][2], 0.f);   v1 = fmaxf(acc2[2*g][3], 0.f);
                    bsplit(v0, h0, l0); bsplit(v1, h1, l1);
                    a3h[1] = bf16bits(h0) | (bf16bits(h1) << 16);
                    a3l[1] = bf16bits(l0) | (bf16bits(l1) << 16);
                    v0 = fmaxf(acc2[2*g+1][0], 0.f); v1 = fmaxf(acc2[2*g+1][1], 0.f);
                    bsplit(v0, h0, l0); bsplit(v1, h1, l1);
                    a3h[2] = bf16bits(h0) | (bf16bits(h1) << 16);
                    a3l[2] = bf16bits(l0) | (bf16bits(l1) << 16);
                    v0 = fmaxf(acc2[2*g+1][2], 0.f); v1 = fmaxf(acc2[2*g+1][3], 0.f);
                    bsplit(v0, h0, l0); bsplit(v1, h1, l1);
                    a3h[3] = bf16bits(h0) | (bf16bits(h1) << 16);
                    a3l[3] = bf16bits(l0) | (bf16bits(l1) << 16);

                    const uint32_t krow3 = (uint32_t)(half * 32 + g * 16 + (lane & 15));
                    #pragma unroll
                    for (int jp3 = 0; jp3 < 7; jp3++) {
                        uint32_t bh[4], bl[4];
                        uint32_t boff = (krow3 * NPAD3 + (uint32_t)(jp3 * 16) + nofs) * 2;
                        ldmx4t(bh, pnl + PNL_B3H + boff);
                        ldmx4t(bl, pnl + PNL_B3L + boff);
                        mma16816(acc3[2*jp3],   a3h, bh);
                        mma16816(acc3[2*jp3+1], a3h, bh + 2);
                        mma16816(acc3[2*jp3],   a3h, bl);
                        mma16816(acc3[2*jp3+1], a3h, bl + 2);
                        mma16816(acc3[2*jp3],   a3l, bh);
                        mma16816(acc3[2*jp3+1], a3l, bh + 2);
                    }
                }
            }
        }
        __syncthreads();   // panel reads done before next-next stage overwrites
    }

    // ---- cross-half reduction of d3, bias, relu -> s_d3 (h3 layout) ----
    if (half == 1) {
        #pragma unroll
        for (int j = 0; j < 14; j++) {
            #pragma unroll
            for (int q = 0; q < 4; q++) {
                int n = 8 * j + tid4 * 2 + (q & 1);
                int row = mrow + gid + ((q >= 2) ? 8 : 0);
                s_d3[row * H3PAD + n] = acc3[j][q];
            }
        }
    }
    __syncthreads();
    if (half == 0) {
        #pragma unroll
        for (int j = 0; j < 14; j++) {
            #pragma unroll
            for (int q = 0; q < 4; q++) {
                int n = 8 * j + tid4 * 2 + (q & 1);
                int row = mrow + gid + ((q >= 2) ? 8 : 0);
                float bias = (n < 100) ? s_b3[n] : 0.f;
                float v = acc3[j][q] + s_d3[row * H3PAD + n] + bias;
                s_d3[row * H3PAD + n] = fmaxf(v, 0.f);
            }
        }
    }
    __syncthreads();

    // ---- layer 4 on cores: h3[128,100] -> pred[128,6] ----
    for (int o = t; o < RPC * 6; o += 512) {
        int r = o / 6, cc = o % 6;
        float acc = s_w4[600 + cc];
        #pragma unroll 4
        for (int k = 0; k < 100; k++) acc += s_d3[r * H3PAD + k] * s_w4[k * 6 + cc];
        s_pred[o] = acc;
    }
    __syncthreads();

    // ---- scatter ----
    if (t < RPC) {
        int row = s_row[t];
        if (row >= 0) {
            float* o = out + (size_t)row * XDIM;
            #pragma unroll
            for (int j = 0; j < 6; j++)
                o[s_idx[t * 8 + j]] = s_att[t * 8 + j] + s_pred[t * 6 + j];
        }
    }
}

// ---------------- launch ----------------
extern "C" void kernel_launch(void* const* d_in, const int* in_sizes, int n_in,
                              void* d_out, int out_size) {
    const float* x   = (const float*)d_in[0];
    const float* W1  = (const float*)d_in[1];
    const float* b1  = (const float*)d_in[2];
    const float* W2  = (const float*)d_in[3];
    const float* b2  = (const float*)d_in[4];
    const float* W3  = (const float*)d_in[5];
    const float* b3  = (const float*)d_in[6];
    const float* W4  = (const float*)d_in[7];
    const float* b4  = (const float*)d_in[8];
    const int*   act = (const int*)d_in[9];
    float* out = (float*)d_out;

    int B = in_sizes[0] / XDIM;

    static bool attr_set = false;
    if (!attr_set) {
        cudaFuncSetAttribute(k4_mlp, cudaFuncAttributeMaxDynamicSharedMemorySize, SMEM_TOTAL);
        attr_set = true;
    }

    int k4_blocks = (B + RPC - 1) / RPC + 3;

    k_wsplit<<<(W2P + 255) / 256, 256>>>(W2, W3);
    k1_prep<<<(B + 7) / 8, 256>>>(x, act, out, B);
    k2_bases<<<1, 32>>>();
    k4_mlp<<<k4_blocks, 512, SMEM_TOTAL>>>(W1, b1, b2, b3, W4, b4, out);
}